// round 13
// baseline (speedup 1.0000x reference)
#include <cuda_runtime.h>
#include <cuda_bf16.h>

#define NROWS  8192
#define DIM    1024
#define NPAIRS 1024
#define SLOTS  64            // P(bucket > 64) < 1e-40 for Poisson(8)
#define MARGIN_RANK 0.05f
#define FULL   0xFFFFFFFFu
#define NBLOCKS (1 + NROWS / 8)   // block 0 = norms, 1..1024 = rows

// ---------------- device scratch (no allocations allowed) ----------------
__device__ float4 g_slot[NPAIRS * SLOTS]; // {sp_raw, sn_raw, lev, 0}
__device__ int    g_flag[NPAIRS * SLOTS]; // slot published flags (reset each launch)
__device__ int    g_bcnt[NPAIRS];         // bucket tickets (reset each launch)
__device__ float  g_invp, g_invn;
__device__ int    g_nrm_ready;            // release flag for norms
__device__ float  g_cons_sum, g_pos_sum, g_neg_sum;
__device__ int    g_cons_cnt, g_rank_cnt;
__device__ int    g_done;

// ---------------- single kernel: GEMV + arrival-time pairs ----------------
__global__ void __launch_bounds__(256) K_all(
    const float4* __restrict__ x, const float4* __restrict__ tp4,
    const float4* __restrict__ tn4, const int* __restrict__ pair,
    const int* __restrict__ lev, float* __restrict__ out)
{
    __shared__ float sacc[5];     // cs, ps, ns, cc, rc (block partials)
    __shared__ int   slast;
    __shared__ float sA[8], sB[8];

    int t = threadIdx.x, lane = t & 31, w = t >> 5;
    if (t < 5)  sacc[t] = 0.f;
    if (t == 5) slast = 0;
    __syncthreads();

    if (blockIdx.x == 0) {
        // ---- text-vector inverse norms, then release ----
        const float* tp = (const float*)tp4;
        const float* tn = (const float*)tn4;
        float pa = 0.f, pb = 0.f;
        #pragma unroll
        for (int j = 0; j < 4; j++) {
            float a = tp[t + j * 256], b = tn[t + j * 256];
            pa += a * a;  pb += b * b;
        }
        #pragma unroll
        for (int o = 16; o; o >>= 1) {
            pa += __shfl_xor_sync(FULL, pa, o);
            pb += __shfl_xor_sync(FULL, pb, o);
        }
        if (lane == 0) { sA[w] = pa; sB[w] = pb; }
        __syncthreads();
        if (t == 0) {
            float qa = 0.f, qb = 0.f;
            #pragma unroll
            for (int j = 0; j < 8; j++) { qa += sA[j]; qb += sB[j]; }
            g_invp = rsqrtf(qa);
            g_invn = rsqrtf(qb);
            __threadfence();
            *((volatile int*)&g_nrm_ready) = 1;   // release
        }
    } else {
        // ---- GEMV: one warp per row ----
        int row = (blockIdx.x - 1) * 8 + w;
        int p = 0, lv = 0;
        if (lane == 0) { p = pair[row]; lv = lev[row]; }   // in flight early

        const float4* r4 = x + (size_t)row * (DIM / 4);
        float4 v[8];
        #pragma unroll
        for (int k = 0; k < 8; k++) v[k] = r4[k * 32 + lane];

        float dp = 0.f, dn = 0.f, dx = 0.f;
        #pragma unroll
        for (int k = 0; k < 8; k++) {
            float4 pt = __ldg(tp4 + k * 32 + lane);
            float4 qt = __ldg(tn4 + k * 32 + lane);
            dp += v[k].x*pt.x + v[k].y*pt.y + v[k].z*pt.z + v[k].w*pt.w;
            dn += v[k].x*qt.x + v[k].y*qt.y + v[k].z*qt.z + v[k].w*qt.w;
            dx += v[k].x*v[k].x + v[k].y*v[k].y + v[k].z*v[k].z + v[k].w*v[k].w;
        }
        #pragma unroll
        for (int o = 16; o; o >>= 1) {
            dp += __shfl_xor_sync(FULL, dp, o);
            dn += __shfl_xor_sync(FULL, dn, o);
            dx += __shfl_xor_sync(FULL, dx, o);
        }

        float spj = 0.f, snj = 0.f, invp = 0.f, invn = 0.f;
        int rank = 0;
        if (lane == 0) {
            float inv = rsqrtf(dx);
            spj = dp * inv;  snj = dn * inv;     // row-normalized raw sims
            // acquire norms (block 0 is in wave 1: bounded wait, no deadlock)
            while (*((volatile int*)&g_nrm_ready) == 0) {}
            __threadfence();
            invp = g_invp;  invn = g_invn;
            // publish this row: ticket -> slot -> fence -> flag
            rank = atomicAdd(&g_bcnt[p], 1);
            if (rank < SLOTS) {
                float4 o4;
                o4.x = spj; o4.y = snj; o4.z = __int_as_float(lv); o4.w = 0.f;
                g_slot[p * SLOTS + rank] = o4;
                __threadfence();
                *((volatile int*)&g_flag[p * SLOTS + rank]) = 1;
            }
        }
        // broadcast row record to all lanes
        rank = __shfl_sync(FULL, rank, 0);
        p    = __shfl_sync(FULL, p,    0);
        lv   = __shfl_sync(FULL, lv,   0);
        spj  = __shfl_sync(FULL, spj,  0);
        snj  = __shfl_sync(FULL, snj,  0);
        invp = __shfl_sync(FULL, invp, 0);
        invn = __shfl_sync(FULL, invn, 0);

        // ---- pair with all EARLIER arrivals of this bucket (one per lane) ----
        int r = rank < SLOTS ? rank : SLOTS;
        float cs = 0.f, ps = 0.f, ns = 0.f;
        float cc = 0.f, rc = 0.f;
        if (lane < r) {
            volatile int* f = &g_flag[p * SLOTS + lane];
            while (*f == 0) {}                   // writer is non-blocking: bounded
            __threadfence();                     // acquire the slot payload
            float4 vi = g_slot[p * SLOTS + lane];
            float spi = vi.x, sni = vi.y;
            int   li  = __float_as_int(vi.z);
            if (li == lv) {
                cs = invp * fabsf(spi - spj) + invn * fabsf(sni - snj);
                cc = 1.f;
            } else if (li < lv) {                // ordered (i earlier-level, j)
                ps = fmaxf(MARGIN_RANK - invp * (spi - spj), 0.f);
                ns = fmaxf(MARGIN_RANK + invn * (sni - snj), 0.f);
                rc = 1.f;
            } else {                             // ordered (j lower level, i)
                ps = fmaxf(MARGIN_RANK - invp * (spj - spi), 0.f);
                ns = fmaxf(MARGIN_RANK + invn * (snj - sni), 0.f);
                rc = 1.f;
            }
        }
        #pragma unroll
        for (int o = 16; o; o >>= 1) {
            cs += __shfl_xor_sync(FULL, cs, o);
            ps += __shfl_xor_sync(FULL, ps, o);
            ns += __shfl_xor_sync(FULL, ns, o);
            cc += __shfl_xor_sync(FULL, cc, o);
            rc += __shfl_xor_sync(FULL, rc, o);
        }
        if (lane == 0 && (cc + rc) > 0.f) {
            atomicAdd(&sacc[0], cs);
            atomicAdd(&sacc[1], ps);
            atomicAdd(&sacc[2], ns);
            atomicAdd(&sacc[3], cc);
            atomicAdd(&sacc[4], rc);
        }
    }

    // ---- block tail: flush partials, detect completion ----
    __syncthreads();
    if (t == 0) {
        if (sacc[3] + sacc[4] > 0.f) {
            atomicAdd(&g_cons_sum, sacc[0]);
            atomicAdd(&g_pos_sum,  sacc[1]);
            atomicAdd(&g_neg_sum,  sacc[2]);
            atomicAdd(&g_cons_cnt, (int)(sacc[3] + 0.5f));
            atomicAdd(&g_rank_cnt, (int)(sacc[4] + 0.5f));
        }
        __threadfence();
        if (atomicAdd(&g_done, 1) == NBLOCKS - 1) slast = 1;
    }
    __syncthreads();

    // ---- last block: finalize + reset ALL state for graph replay ----
    if (slast) {
        for (int i = t; i < NPAIRS * SLOTS; i += 256) g_flag[i] = 0;
        for (int i = t; i < NPAIRS; i += 256)         g_bcnt[i] = 0;
        if (t == 0) {
            __threadfence();
            float lc = (g_cons_cnt > 0) ? g_cons_sum / (float)(2 * g_cons_cnt) : 0.f;
            float lp = (g_rank_cnt > 0) ? g_pos_sum  / (float)g_rank_cnt       : 0.f;
            float ln = (g_rank_cnt > 0) ? g_neg_sum  / (float)g_rank_cnt       : 0.f;
            out[0] = lc + lp + ln;
            g_cons_sum = 0.f; g_pos_sum = 0.f; g_neg_sum = 0.f;
            g_cons_cnt = 0;   g_rank_cnt = 0;
            g_done = 0;       g_nrm_ready = 0;
        }
    }
}

// ---------------- launch ---------------------------------------------------
extern "C" void kernel_launch(void* const* d_in, const int* in_sizes, int n_in,
                              void* d_out, int out_size) {
    const float* img  = (const float*)d_in[0];  // [8192, 1024]
    const float* tp   = (const float*)d_in[1];  // [1024]
    const float* tn   = (const float*)d_in[2];  // [1024]
    const int*   lev  = (const int*)  d_in[3];  // [8192]
    const int*   pair = (const int*)  d_in[4];  // [8192]
    float* out = (float*)d_out;

    K_all<<<NBLOCKS, 256>>>(
        (const float4*)img, (const float4*)tp, (const float4*)tn, pair, lev, out);
}

// round 15
// speedup vs baseline: 1.2837x; 1.2837x over previous
#include <cuda_runtime.h>
#include <cuda_bf16.h>

#define NROWS  8192
#define DIM    1024
#define NPAIRS 1024
#define SLOTS  32            // fixed bin capacity; P(overflow) ~ 1e-8 (Poisson 8)
#define MARGIN_RANK 0.05f
#define FULL   0xFFFFFFFFu
#define RPB    16            // rows per block (2 batches of 8)
#define BATCH  8

// ---------------- device scratch (no allocations allowed) ----------------
__device__ float  g_sp[NROWS];             // raw row-normalized sims (fallback)
__device__ float  g_sn[NROWS];
__device__ int    g_bcnt[NPAIRS];          // counts; read+reset by K2 each launch
__device__ float4 g_slot[NPAIRS * SLOTS];  // direct-addressed bins {sp, sn, lev, 0}
__device__ float  g_cons_sum, g_pos_sum, g_neg_sum;
__device__ int    g_cons_cnt, g_rank_cnt;
__device__ int    g_done;

// ---------------- K1: slice-per-warp GEMV (text vectors in registers) -----
// 512 blocks x 256 threads. Warp w owns dims [w*128, w*128+128): its lane
// text float4s live in registers for the whole block. The block covers each
// row cooperatively; 8 rows per batch give MLP=8 per lane on row data.
// Per-row l1tex traffic = row data only (32 wavefronts, the minimum).
__global__ void __launch_bounds__(256) K1_gemv(
    const float4* __restrict__ x, const float4* __restrict__ tp4,
    const float4* __restrict__ tn4, const int* __restrict__ pair,
    const int* __restrict__ lev)
{
    __shared__ float part[3][BATCH][8];   // [dp|dn|dx][row][warp]
    __shared__ int   spair[RPB], slev[RPB];

    int t = threadIdx.x, lane = t & 31, w = t >> 5;
    int rbase = blockIdx.x * RPB;

    // per-lane text slice: registers, reused for all 16 rows
    float4 p = tp4[w * 32 + lane];
    float4 q = tn4[w * 32 + lane];

    if (t < RPB) { spair[t] = pair[rbase + t]; slev[t] = lev[rbase + t]; }

    #pragma unroll
    for (int batch = 0; batch < RPB / BATCH; batch++) {
        int r0 = rbase + batch * BATCH;

        // 8 independent row-slice loads in flight
        float4 v[BATCH];
        #pragma unroll
        for (int r = 0; r < BATCH; r++)
            v[r] = x[(size_t)(r0 + r) * (DIM / 4) + w * 32 + lane];

        float aP[BATCH], aN[BATCH], aX[BATCH];
        #pragma unroll
        for (int r = 0; r < BATCH; r++) {
            aP[r] = v[r].x*p.x + v[r].y*p.y + v[r].z*p.z + v[r].w*p.w;
            aN[r] = v[r].x*q.x + v[r].y*q.y + v[r].z*q.z + v[r].w*q.w;
            aX[r] = v[r].x*v[r].x + v[r].y*v[r].y + v[r].z*v[r].z + v[r].w*v[r].w;
        }

        // 24 independent reduction chains, fully pipelined shuffles
        #pragma unroll
        for (int o = 16; o; o >>= 1) {
            #pragma unroll
            for (int r = 0; r < BATCH; r++) {
                aP[r] += __shfl_xor_sync(FULL, aP[r], o);
                aN[r] += __shfl_xor_sync(FULL, aN[r], o);
                aX[r] += __shfl_xor_sync(FULL, aX[r], o);
            }
        }
        if (lane == 0) {
            #pragma unroll
            for (int r = 0; r < BATCH; r++) {
                part[0][r][w] = aP[r];
                part[1][r][w] = aN[r];
                part[2][r][w] = aX[r];
            }
        }
        __syncthreads();

        // 8 lanes finalize 8 rows: combine 8 warp-partials, scatter to bin
        if (t < BATCH) {
            float dp = 0.f, dn = 0.f, dx = 0.f;
            #pragma unroll
            for (int j = 0; j < 8; j++) {
                dp += part[0][t][j];
                dn += part[1][t][j];
                dx += part[2][t][j];
            }
            int row = r0 + t;
            float inv = rsqrtf(dx);
            float sp = dp * inv, sn = dn * inv;     // raw (text norm in K2)
            g_sp[row] = sp;                          // overflow-fallback copy
            g_sn[row] = sn;
            int pp = spair[batch * BATCH + t];
            int lv = slev[batch * BATCH + t];
            int rank = atomicAdd(&g_bcnt[pp], 1);
            if (rank < SLOTS) {
                float4 o4;
                o4.x = sp; o4.y = sn; o4.z = __int_as_float(lv); o4.w = 0.f;
                g_slot[pp * SLOTS + rank] = o4;
            }
        }
        __syncthreads();
    }
}

// ---------------- K2: warp-per-bucket shuffle all-pairs + finalize --------
// 128 blocks x 256 threads. Each block redundantly computes the text
// inverse-norms (L2-hot, removes the cross-kernel dependency). Lane 0
// reads+resets its bucket count; lanes read the bin coalesced; pure
// shuffle all-pairs; last block finalizes and resets state for replay.
__global__ void __launch_bounds__(256) K2_pairs(
    const float* __restrict__ tp, const float* __restrict__ tn,
    const int* __restrict__ pair, const int* __restrict__ lev,
    float* __restrict__ out)
{
    __shared__ float sA[8], sB[8];
    __shared__ float sinv[2];

    int t = threadIdx.x, lane = t & 31, w = t >> 5;

    // redundant per-block text inverse-norms
    float pa = 0.f, pb = 0.f;
    #pragma unroll
    for (int j = 0; j < 4; j++) {
        float a = tp[t + j * 256], b = tn[t + j * 256];
        pa += a * a;  pb += b * b;
    }
    #pragma unroll
    for (int o = 16; o; o >>= 1) {
        pa += __shfl_xor_sync(FULL, pa, o);
        pb += __shfl_xor_sync(FULL, pb, o);
    }
    if (lane == 0) { sA[w] = pa; sB[w] = pb; }
    __syncthreads();
    if (t == 0) {
        float qa = 0.f, qb = 0.f;
        #pragma unroll
        for (int j = 0; j < 8; j++) { qa += sA[j]; qb += sB[j]; }
        sinv[0] = rsqrtf(qa);
        sinv[1] = rsqrtf(qb);
    }
    __syncthreads();
    float invp = sinv[0], invn = sinv[1];

    int wg = blockIdx.x * 8 + w;
    int c = 0;
    if (lane == 0) { c = g_bcnt[wg]; g_bcnt[wg] = 0; }   // read then reset
    c = __shfl_sync(FULL, c, 0);

    float cs = 0.f, ps = 0.f, ns = 0.f;
    int cc = 0, rc = 0;

    if (c <= SLOTS) {
        float sp = 0.f, sn = 0.f; int lv = 0;
        bool act = lane < c;
        if (act) {
            float4 va = g_slot[wg * SLOTS + lane];       // coalesced 512B
            sp = va.x * invp; sn = va.y * invn; lv = __float_as_int(va.z);
        }
        for (int b = 0; b < c; b++) {
            float spb = __shfl_sync(FULL, sp, b);
            float snb = __shfl_sync(FULL, sn, b);
            int   lb  = __shfl_sync(FULL, lv, b);
            if (act && lv == lb && lane < b) {
                cs += fabsf(sp - spb) + fabsf(sn - snb);
                cc++;
            }
            if (act && lv < lb) {
                ps += fmaxf(MARGIN_RANK - (sp - spb), 0.f);
                ns += fmaxf(MARGIN_RANK + (sn - snb), 0.f);
                rc++;
            }
        }
    } else {
        // astronomically-unlikely overflow: correct-but-slow row scan
        for (int i = lane; i < NROWS; i += 32) {
            if (pair[i] != wg) continue;
            float spa = g_sp[i] * invp, sna = g_sn[i] * invn;
            int   la  = lev[i];
            for (int j = 0; j < NROWS; j++) {
                if (pair[j] != wg) continue;
                float spb = g_sp[j] * invp, snb = g_sn[j] * invn;
                int   lb  = lev[j];
                if (la == lb && i < j) {
                    cs += fabsf(spa - spb) + fabsf(sna - snb);
                    cc++;
                }
                if (la < lb) {
                    ps += fmaxf(MARGIN_RANK - (spa - spb), 0.f);
                    ns += fmaxf(MARGIN_RANK + (sna - snb), 0.f);
                    rc++;
                }
            }
        }
    }

    #pragma unroll
    for (int o = 16; o; o >>= 1) {
        cs += __shfl_xor_sync(FULL, cs, o);
        ps += __shfl_xor_sync(FULL, ps, o);
        ns += __shfl_xor_sync(FULL, ns, o);
        cc += __shfl_xor_sync(FULL, cc, o);
        rc += __shfl_xor_sync(FULL, rc, o);
    }
    if (lane == 0 && (cc | rc)) {
        atomicAdd(&g_cons_sum, cs);
        atomicAdd(&g_pos_sum,  ps);
        atomicAdd(&g_neg_sum,  ns);
        atomicAdd(&g_cons_cnt, cc);
        atomicAdd(&g_rank_cnt, rc);
    }

    // fused finalize: last block writes the scalar + resets state for replay
    __syncthreads();
    if (t == 0) {
        __threadfence();
        if (atomicAdd(&g_done, 1) == (int)gridDim.x - 1) {
            __threadfence();
            float lc = (g_cons_cnt > 0) ? g_cons_sum / (float)(2 * g_cons_cnt) : 0.f;
            float lp = (g_rank_cnt > 0) ? g_pos_sum  / (float)g_rank_cnt       : 0.f;
            float ln = (g_rank_cnt > 0) ? g_neg_sum  / (float)g_rank_cnt       : 0.f;
            out[0] = lc + lp + ln;
            g_cons_sum = 0.f; g_pos_sum = 0.f; g_neg_sum = 0.f;
            g_cons_cnt = 0;   g_rank_cnt = 0;  g_done = 0;
        }
    }
}

// ---------------- launch ---------------------------------------------------
extern "C" void kernel_launch(void* const* d_in, const int* in_sizes, int n_in,
                              void* d_out, int out_size) {
    const float* img  = (const float*)d_in[0];  // [8192, 1024]
    const float* tp   = (const float*)d_in[1];  // [1024]
    const float* tn   = (const float*)d_in[2];  // [1024]
    const int*   lev  = (const int*)  d_in[3];  // [8192]
    const int*   pair = (const int*)  d_in[4];  // [8192]
    float* out = (float*)d_out;

    K1_gemv<<<NROWS / RPB, 256>>>(
        (const float4*)img, (const float4*)tp, (const float4*)tn, pair, lev);
    K2_pairs<<<NPAIRS / 8, 256>>>(tp, tn, pair, lev, out);
}